// round 1
// baseline (speedup 1.0000x reference)
#include <cuda_runtime.h>
#include <cstdint>

#define B_ 4
#define N_ 8192
#define C_ 64
#define K_ 16
#define O_ 128

// ---------------- scratch (no allocs allowed) ----------------
__device__ float g_feats[B_ * N_ * C_];   // (b, n, c) row-major, 8 MB
__device__ float g_xx[B_ * N_];           // squared norms
__device__ int   g_knn[B_ * N_ * K_];     // top-16 neighbor indices

typedef unsigned long long u64;

// ---------------- packed f32x2 helpers (sm_103a) ----------------
__device__ __forceinline__ u64 fma2(u64 a, u64 b, u64 c) {
    u64 d;
    asm("fma.rn.f32x2 %0, %1, %2, %3;" : "=l"(d) : "l"(a), "l"(b), "l"(c));
    return d;
}
__device__ __forceinline__ u64 add2(u64 a, u64 b) {
    u64 d;
    asm("add.rn.f32x2 %0, %1, %2;" : "=l"(d) : "l"(a), "l"(b));
    return d;
}
__device__ __forceinline__ float plo(u64 v) { return __uint_as_float((unsigned)v); }
__device__ __forceinline__ float phi(u64 v) { return __uint_as_float((unsigned)(v >> 32)); }
__device__ __forceinline__ float psum(u64 v) { return plo(v) + phi(v); }

// ---------------- kernel 1: transpose x -> feats, compute ||x||^2 ----------------
__global__ void __launch_bounds__(256) prep_kernel(const float* __restrict__ x) {
    int idx = blockIdx.x * 256 + threadIdx.x;      // 0 .. B*N-1
    int b = idx >> 13;
    int n = idx & (N_ - 1);
    const float* xb = x + (size_t)b * C_ * N_ + n;
    float v[C_];
    float acc = 0.f;
#pragma unroll
    for (int c = 0; c < C_; ++c) {
        float t = xb[(size_t)c * N_];              // coalesced across threads (consecutive n)
        v[c] = t;
        acc = fmaf(t, t, acc);
    }
    float4* fp = reinterpret_cast<float4*>(g_feats + (size_t)idx * C_);
#pragma unroll
    for (int i = 0; i < C_ / 4; ++i)
        fp[i] = make_float4(v[4 * i], v[4 * i + 1], v[4 * i + 2], v[4 * i + 3]);
    g_xx[idx] = acc;
}

// ---------------- kernel 2: brute-force KNN (top-16 per point) ----------------
#define KT   128   // threads = queries per block
#define TILE 64    // candidates per smem tile

__global__ void __launch_bounds__(KT) knn_kernel() {
    __shared__ __align__(16) float s_feat[TILE * C_];   // 16 KB
    __shared__ float s_sx[TILE];
    __shared__ float s_val[KT * 16];                    // 8 KB sorted desc
    __shared__ int   s_idx[KT * 16];                    // 8 KB

    int b = blockIdx.y;
    int t = threadIdx.x;
    int q = blockIdx.x * KT + t;
    const float* fb = g_feats + (size_t)b * N_ * C_;

    // query features, packed as f32x2
    u64 q2[C_ / 2];
    {
        const u64* qp = reinterpret_cast<const u64*>(fb + (size_t)q * C_);
#pragma unroll
        for (int i = 0; i < C_ / 2; ++i) q2[i] = qp[i];
    }
    float qxx = g_xx[b * N_ + q];

    float* mv = s_val + t * 16;
    int*   mi = s_idx + t * 16;
#pragma unroll
    for (int i = 0; i < 16; ++i) { mv[i] = -3.4e38f; mi[i] = 0; }
    float thr = -3.4e38f;

    for (int tile = 0; tile < N_ / TILE; ++tile) {
        __syncthreads();
        // cooperative tile load: TILE*C_/4 = 1024 float4, 8 per thread, coalesced
        const float4* src = reinterpret_cast<const float4*>(fb + (size_t)tile * TILE * C_);
        float4* dst = reinterpret_cast<float4*>(s_feat);
#pragma unroll
        for (int i = 0; i < (TILE * C_ / 4) / KT; ++i)
            dst[t + i * KT] = src[t + i * KT];
        if (t < TILE) s_sx[t] = g_xx[b * N_ + tile * TILE + t];
        __syncthreads();

#pragma unroll 1
        for (int j = 0; j < TILE; ++j) {
            // uniform-address broadcast LDS.128 reads of candidate row
            const ulonglong2* sp = reinterpret_cast<const ulonglong2*>(s_feat + j * C_);
            u64 a0 = 0, a1 = 0, a2 = 0, a3 = 0;
#pragma unroll
            for (int i = 0; i < 8; ++i) {
                ulonglong2 u = sp[2 * i];
                ulonglong2 w = sp[2 * i + 1];
                a0 = fma2(q2[4 * i + 0], u.x, a0);
                a1 = fma2(q2[4 * i + 1], u.y, a1);
                a2 = fma2(q2[4 * i + 2], w.x, a2);
                a3 = fma2(q2[4 * i + 3], w.y, a3);
            }
            u64 s = add2(add2(a0, a1), add2(a2, a3));
            float sum = psum(s);
            float d = 2.f * sum - (qxx + s_sx[j]);   // neg squared distance

            if (d > thr) {                            // rare (~1.4%/lane)
                int jj = tile * TILE + j;
                int p = 15;
                // strict '<' keeps equal-valued earlier (lower) indices above,
                // matching jax.lax.top_k tie-breaking.
                while (p > 0 && mv[p - 1] < d) {
                    mv[p] = mv[p - 1];
                    mi[p] = mi[p - 1];
                    --p;
                }
                mv[p] = d;
                mi[p] = jj;
                thr = mv[15];
            }
        }
    }

    int* og = g_knn + (size_t)(b * N_ + q) * K_;
#pragma unroll
    for (int i = 0; i < 16; ++i) og[i] = mi[i];
}

// ---------------- kernel 3: edge conv + max pool ----------------
#define CT  128   // threads = output channels
#define PPB 64    // points per block

__device__ __forceinline__ void cv_issue(const float* fb, const int* s_nidx,
                                         int p0, int pl, int t,
                                         float4* rn, float4* rx) {
#pragma unroll
    for (int s = 0; s < 3; ++s) {
        if (s == 2 && t >= 16) continue;
        int cid = t + s * CT;          // 0..271 : 17 rows x 16 float4
        int r = cid >> 4, c4 = cid & 15;
        const float4* xrow = reinterpret_cast<const float4*>(fb + (size_t)(p0 + pl) * C_);
        if (r < 16) {
            int nj = s_nidx[pl * K_ + r];
            rn[s] = reinterpret_cast<const float4*>(fb + (size_t)nj * C_)[c4];
            rx[s] = xrow[c4];
        } else {
            rn[s] = xrow[c4];          // row 16 = x_i itself
        }
    }
}

__device__ __forceinline__ void cv_commit(float4* buf, int t,
                                          const float4* rn, const float4* rx) {
#pragma unroll
    for (int s = 0; s < 3; ++s) {
        if (s == 2 && t >= 16) continue;
        int cid = t + s * CT;
        int r = cid >> 4, c4 = cid & 15;
        float4 v = rn[s];
        if (r < 16) { v.x -= rx[s].x; v.y -= rx[s].y; v.z -= rx[s].z; v.w -= rx[s].w; }
        buf[r * 16 + c4] = v;
    }
}

__global__ void __launch_bounds__(CT) conv_kernel(const float* __restrict__ W,
                                                  const float* __restrict__ bias,
                                                  float* __restrict__ out) {
    __shared__ float4 sbuf[2][17 * 16];      // double-buffered staged point data
    __shared__ int s_nidx[PPB * K_];

    int b = blockIdx.y;
    int p0 = blockIdx.x * PPB;
    int t = threadIdx.x;                     // output channel
    const float* fb = g_feats + (size_t)b * N_ * C_;

    // W row for this channel, packed f32x2: w2[0..31] = W1 (x_i part), w2[32..63] = W2 (diff part)
    u64 w2[64];
    {
        const u64* wp = reinterpret_cast<const u64*>(W + (size_t)t * 2 * C_);
#pragma unroll
        for (int i = 0; i < 64; ++i) w2[i] = wp[i];
    }
    float bo = bias[t];

    for (int i = t; i < PPB * K_; i += CT)
        s_nidx[i] = g_knn[(size_t)(b * N_ + p0) * K_ + i];
    __syncthreads();

    float4 rn[3], rx[3];
    cv_issue(fb, s_nidx, p0, 0, t, rn, rx);

    for (int pl = 0; pl < PPB; ++pl) {
        float4* buf = sbuf[pl & 1];
        cv_commit(buf, t, rn, rx);
        __syncthreads();
        if (pl + 1 < PPB) cv_issue(fb, s_nidx, p0, pl + 1, t, rn, rx);  // prefetch next point

        const ulonglong2* base = reinterpret_cast<const ulonglong2*>(buf);

        // a-term: W1 . x_i   (row 16)
        u64 a0 = 0, a1 = 0;
#pragma unroll
        for (int i = 0; i < 16; ++i) {
            ulonglong2 u = base[16 * 16 + i];
            a0 = fma2(w2[2 * i], u.x, a0);
            a1 = fma2(w2[2 * i + 1], u.y, a1);
        }
        float aterm = psum(add2(a0, a1));

        // max_k W2 . (x_j - x_i)
        float m = -3.4e38f;
#pragma unroll
        for (int k = 0; k < 16; ++k) {
            u64 c0 = 0, c1 = 0;
#pragma unroll
            for (int i = 0; i < 16; ++i) {
                ulonglong2 u = base[k * 16 + i];
                c0 = fma2(w2[32 + 2 * i], u.x, c0);
                c1 = fma2(w2[33 + 2 * i], u.y, c1);
            }
            float tk = psum(add2(c0, c1));
            m = fmaxf(m, tk);
        }

        out[(size_t)(b * O_ + t) * N_ + p0 + pl] = aterm + m + bo;
    }
}

// ---------------- launch ----------------
extern "C" void kernel_launch(void* const* d_in, const int* in_sizes, int n_in,
                              void* d_out, int out_size) {
    (void)in_sizes; (void)n_in; (void)out_size;
    const float* x    = (const float*)d_in[0];   // (4, 64, 8192, 1)
    const float* W    = (const float*)d_in[1];   // (128, 128)
    const float* bias = (const float*)d_in[2];   // (128,)
    float* out = (float*)d_out;                  // (4, 128, 8192, 1)

    prep_kernel<<<(B_ * N_) / 256, 256>>>(x);
    knn_kernel<<<dim3(N_ / KT, B_), KT>>>();
    conv_kernel<<<dim3(N_ / PPB, B_), CT>>>(W, bias, out);
}